// round 15
// baseline (speedup 1.0000x reference)
#include <cuda_runtime.h>
#include <cstdint>

// Problem constants (fixed by the dataset)
#define N_  50000
#define E_  600000
#define F_  64
#define H_  128
#define RDIM 256     // GEMM K dim: 4 cheb orders * 64 feats
#define CDIM 256     // GEMM N dim: 128 (z) + 128 (h)
#define KC   32      // K chunk per SMEM stage
#define NCHUNK (RDIM / KC)   // 8

// ---------------- device scratch ----------------
__device__ float g_deg[N_];
__device__ int   g_cnt[N_];
__device__ int   g_cur[N_];
__device__ int   g_off[N_ + 1];
__device__ int   g_csrc[E_];
__device__ float g_cw[E_];
__device__ int   g_fail;               // mma verification flag
__device__ __align__(16) float g_T1[N_ * F_];
__device__ __align__(16) float g_T2[N_ * F_];
__device__ __align__(16) float g_T3[N_ * F_];
// B^T in tf32 bit patterns (hi and lo halves of the fp32 weights):
// g_Bt*[n*256 + kq], n = output col (0..255), kq = k*64+f  (= Wcat[kq][n])
__device__ __align__(16) uint32_t g_Bth[CDIM * RDIM];
__device__ __align__(16) uint32_t g_Btl[CDIM * RDIM];
// fallback FFMA weight layout (R1): g_W4[q*1024 + c*4 + (r&3)] = Wcat[r][c]
__device__ __align__(16) float g_W4[RDIM * CDIM];

// ---------------- helpers ----------------
__device__ __forceinline__ uint32_t f2tf32(float f) {
    uint32_t r; asm("cvt.rna.tf32.f32 %0, %1;" : "=r"(r) : "f"(f)); return r;
}

// Standard PTX (sm_80+) tensor-core MMA: D(16x8) += A(16x8,row) * B(8x8,col).
// tf32 inputs as .b32 bit patterns, fp32 accumulate.
__device__ __forceinline__ void mma16n8k8(float* d, const uint32_t* a,
                                          uint32_t b0, uint32_t b1) {
    asm volatile(
        "mma.sync.aligned.m16n8k8.row.col.f32.tf32.tf32.f32 "
        "{%0,%1,%2,%3}, {%4,%5,%6,%7}, {%8,%9}, {%0,%1,%2,%3};"
        : "+f"(d[0]), "+f"(d[1]), "+f"(d[2]), "+f"(d[3])
        : "r"(a[0]), "r"(a[1]), "r"(a[2]), "r"(a[3]), "r"(b0), "r"(b1));
}

// ---------------- setup: zero arrays + build B^T hi/lo (tf32) + g_W4 ----------------
__global__ void k_setup(const float* __restrict__ Wxz, const float* __restrict__ Wxh) {
    int i = blockIdx.x * blockDim.x + threadIdx.x;
    if (i == 0) g_fail = 0;
    if (i < N_) { g_deg[i] = 0.f; g_cnt[i] = 0; g_cur[i] = 0; }
    if (i < CDIM * RDIM) {
        // B^T (hi/lo tf32): g_Bt*[n*256+kq] = Wcat[kq][n]
        {
            int n = i >> 8, kq = i & 255;
            int k = kq >> 6, f = kq & 63;
            float v = (n < H_) ? Wxz[(k * F_ + f) * H_ + n]
                               : Wxh[(k * F_ + f) * H_ + (n - H_)];
            uint32_t hi = f2tf32(v);
            g_Bth[i] = hi;
            g_Btl[i] = f2tf32(v - __uint_as_float(hi));
        }
        // fallback FFMA layout
        {
            int q = i >> 10, rem = i & 1023;
            int c = rem >> 2, rr = rem & 3;
            int r = (q << 2) + rr;
            int k = r >> 6, f = r & 63;
            float v = (c < H_) ? Wxz[(k * F_ + f) * H_ + c]
                               : Wxh[(k * F_ + f) * H_ + (c - H_)];
            g_W4[i] = v;
        }
    }
}

// deg (by src) + in-degree counts (by dst)
__global__ void k_edge1(const int* __restrict__ ei, const float* __restrict__ ew) {
    int e = blockIdx.x * blockDim.x + threadIdx.x;
    if (e >= E_) return;
    int s = ei[e], d = ei[E_ + e];
    float w = (s == d) ? 0.f : ew[e];
    if (w != 0.f) atomicAdd(&g_deg[s], w);
    atomicAdd(&g_cnt[d], 1);
}

// blocks 0..48: dis = rsqrt(deg); block 49: exclusive scan cnt -> off
__global__ void k_disscan() {
    if (blockIdx.x < 49) {
        int i = blockIdx.x * 1024 + threadIdx.x;
        if (i < N_) {
            float dg = g_deg[i];
            g_deg[i] = (dg > 0.f) ? rsqrtf(dg) : 0.f;
        }
        return;
    }
    const int TPB = 1024;
    __shared__ int ssum[TPB];
    int tid = threadIdx.x;
    const int chunk = (N_ + TPB - 1) / TPB;
    int beg = tid * chunk;
    int local = 0;
    for (int i = 0; i < chunk; i++) {
        int idx = beg + i;
        if (idx < N_) local += g_cnt[idx];
    }
    ssum[tid] = local;
    __syncthreads();
    for (int d = 1; d < TPB; d <<= 1) {
        int t = (tid >= d) ? ssum[tid - d] : 0;
        __syncthreads();
        if (tid >= d) ssum[tid] += t;
        __syncthreads();
    }
    int run = ssum[tid] - local;
    for (int i = 0; i < chunk; i++) {
        int idx = beg + i;
        if (idx < N_) { g_off[idx] = run; run += g_cnt[idx]; }
    }
    if (tid == TPB - 1) g_off[N_] = ssum[TPB - 1];
}

__global__ void k_scatter(const int* __restrict__ ei, const float* __restrict__ ew) {
    int e = blockIdx.x * blockDim.x + threadIdx.x;
    if (e >= E_) return;
    int s = ei[e], d = ei[E_ + e];
    float w = (s == d) ? 0.f : ew[e];
    float we = -g_deg[s] * w * g_deg[d];   // g_deg holds dis here
    int pos = atomicAdd(&g_cur[d], 1);
    int o = g_off[d] + pos;
    g_csrc[o] = s;
    g_cw[o]   = we;
}

// ---------------- Chebyshev propagation (gather, no float atomics) ----------------
__global__ void k_prop(const float* __restrict__ x, int step) {
    int t = blockIdx.x * blockDim.x + threadIdx.x;
    if (t >= N_ * 16) return;
    int node = t >> 4;
    int c    = (t & 15) << 2;

    const float* in;  const float* sub;  float* out;  float coef;
    if (step == 0)      { in = x;    sub = nullptr; out = g_T1; coef = 1.f; }
    else if (step == 1) { in = g_T1; sub = x;       out = g_T2; coef = 2.f; }
    else                { in = g_T2; sub = g_T1;    out = g_T3; coef = 2.f; }

    int beg = g_off[node], end = g_off[node + 1];
    float4 acc = make_float4(0.f, 0.f, 0.f, 0.f);
    for (int o = beg; o < end; o++) {
        int   s = g_csrc[o];
        float w = g_cw[o];
        float4 xv = *reinterpret_cast<const float4*>(in + (size_t)s * F_ + c);
        acc.x += w * xv.x; acc.y += w * xv.y;
        acc.z += w * xv.z; acc.w += w * xv.w;
    }
    float4 sv = make_float4(0.f, 0.f, 0.f, 0.f);
    if (sub) sv = *reinterpret_cast<const float4*>(sub + (size_t)node * F_ + c);
    float4 r;
    r.x = coef * acc.x - sv.x;  r.y = coef * acc.y - sv.y;
    r.z = coef * acc.z - sv.z;  r.w = coef * acc.w - sv.w;
    *reinterpret_cast<float4*>(out + (size_t)node * F_ + c) = r;
}

// ---------------- mma.sync tf32 GEMM + fused GRU epilogue ----------------
// Per CTA (512 threads, 16 warps): M tile = 128 nodes, N = 256 (z||h), K = 256.
// 3-pass compensated tf32: D += Ahi*Bhi + Alo*Bhi + Ahi*Blo.
// Warp w: M-strip = (w&7)*16; tile pairs tp in [ (w>>3)*8, +8 ):
//   z-tile cols [tp*8, tp*8+8), h-tile cols [128+tp*8, ...). Pairing z/h in the
//   same thread lets the GRU epilogue combine them locally.
// SMEM (dynamic): A fp32 [128][33] | Bhi u32 [256][33] | Blo u32 [256][33]
#define A_PITCH 33
#define A_WORDS (128 * A_PITCH)          // 4224
#define B_WORDS (256 * A_PITCH)          // 8448
#define OFF_A   0
#define OFF_BH  (A_WORDS)
#define OFF_BL  (A_WORDS + B_WORDS)
#define GEMM_DYN_BYTES ((A_WORDS + 2 * B_WORDS) * 4)   // 84480

extern __shared__ __align__(16) uint32_t dynsm[];

__global__ void __launch_bounds__(512, 1) k_gemm_mma(
    const float* __restrict__ x,
    const float* __restrict__ bxz, const float* __restrict__ bhz,
    const float* __restrict__ bxh, const float* __restrict__ bhh,
    const float* __restrict__ linW, const float* __restrict__ linb,
    float* __restrict__ out)
{
    __shared__ float s_bz[H_], s_bh[H_], s_lw[H_], s_out[128];

    float* sA  = reinterpret_cast<float*>(dynsm + OFF_A);
    uint32_t* sBh = dynsm + OFF_BH;
    uint32_t* sBl = dynsm + OFF_BL;

    const int tid  = threadIdx.x;
    const int warp = tid >> 5;
    const int lane = tid & 31;
    const int g    = lane >> 2;       // group id (row within 8)
    const int tig  = lane & 3;        // thread in group (col within 4)
    const int strip = warp & 7;       // M strip: rows [strip*16, +16)
    const int pb    = (warp >> 3) * 8;  // first tile pair
    const int node0 = blockIdx.x * 128;

    if (tid < H_) {
        s_bz[tid] = bxz[tid] + bhz[tid];
        s_bh[tid] = bxh[tid] + bhh[tid];
        s_lw[tid] = linW[tid];
        s_out[tid] = 0.f;
    }
    const float lb = linb[0];

    float Cz[8][4], Ch[8][4];
    #pragma unroll
    for (int p = 0; p < 8; p++)
        #pragma unroll
        for (int i = 0; i < 4; i++) { Cz[p][i] = 0.f; Ch[p][i] = 0.f; }

    for (int c = 0; c < NCHUNK; c++) {
        const float* in = (c < 2) ? x : (c < 4) ? g_T1 : (c < 6) ? g_T2 : g_T3;
        int f0 = (c & 1) * KC;

        // stage A chunk: [128 rows][32 cols] fp32
        #pragma unroll
        for (int v = tid; v < 1024; v += 512) {
            int r = v >> 3, q = v & 7;
            int node = node0 + r;
            float4 a = make_float4(0.f, 0.f, 0.f, 0.f);
            if (node < N_)
                a = *reinterpret_cast<const float4*>(in + (size_t)node * F_ + f0 + q * 4);
            float* dst = sA + r * A_PITCH + q * 4;
            dst[0] = a.x; dst[1] = a.y; dst[2] = a.z; dst[3] = a.w;
        }
        // stage B chunk: [256 n][32 k] hi + lo
        #pragma unroll
        for (int u = tid; u < 2048; u += 512) {
            int n = u >> 3, q = u & 7;
            size_t gi = (size_t)n * RDIM + c * KC + q * 4;
            uint4 bh4 = *reinterpret_cast<const uint4*>(g_Bth + gi);
            uint4 bl4 = *reinterpret_cast<const uint4*>(g_Btl + gi);
            uint32_t* dh = sBh + n * A_PITCH + q * 4;
            uint32_t* dl = sBl + n * A_PITCH + q * 4;
            dh[0] = bh4.x; dh[1] = bh4.y; dh[2] = bh4.z; dh[3] = bh4.w;
            dl[0] = bl4.x; dl[1] = bl4.y; dl[2] = bl4.z; dl[3] = bl4.w;
        }
        __syncthreads();

        // A fragments for the 4 k-steps (hi/lo tf32)
        uint32_t ahi[4][4], alo[4][4];
        #pragma unroll
        for (int kk = 0; kk < 4; kk++) {
            int base = (strip * 16 + g) * A_PITCH + kk * 8 + tig;
            float a0 = sA[base];                  // row g,   col tig
            float a1 = sA[base + 8 * A_PITCH];    // row g+8, col tig
            float a2 = sA[base + 4];              // row g,   col tig+4
            float a3 = sA[base + 8 * A_PITCH + 4];
            ahi[kk][0] = f2tf32(a0); alo[kk][0] = f2tf32(a0 - __uint_as_float(ahi[kk][0]));
            ahi[kk][1] = f2tf32(a1); alo[kk][1] = f2tf32(a1 - __uint_as_float(ahi[kk][1]));
            ahi[kk][2] = f2tf32(a2); alo[kk][2] = f2tf32(a2 - __uint_as_float(ahi[kk][2]));
            ahi[kk][3] = f2tf32(a3); alo[kk][3] = f2tf32(a3 - __uint_as_float(ahi[kk][3]));
        }

        #pragma unroll
        for (int p = 0; p < 8; p++) {
            int nz = (pb + p) * 8;        // z-tile col base
            int nh = 128 + (pb + p) * 8;  // h-tile col base
            #pragma unroll
            for (int kk = 0; kk < 4; kk++) {
                int bo = kk * 8 + tig;
                // z tile
                {
                    int bi = (nz + g) * A_PITCH + bo;
                    uint32_t bh0 = sBh[bi], bh1 = sBh[bi + 4];
                    mma16n8k8(Cz[p], ahi[kk], bh0, bh1);
                    mma16n8k8(Cz[p], alo[kk], bh0, bh1);
                    uint32_t bl0 = sBl[bi], bl1 = sBl[bi + 4];
                    mma16n8k8(Cz[p], ahi[kk], bl0, bl1);
                }
                // h tile
                {
                    int bi = (nh + g) * A_PITCH + bo;
                    uint32_t bh0 = sBh[bi], bh1 = sBh[bi + 4];
                    mma16n8k8(Ch[p], ahi[kk], bh0, bh1);
                    mma16n8k8(Ch[p], alo[kk], bh0, bh1);
                    uint32_t bl0 = sBl[bi], bl1 = sBl[bi + 4];
                    mma16n8k8(Ch[p], ahi[kk], bl0, bl1);
                }
            }
        }
        __syncthreads();
    }

    // ---- fused GRU epilogue + lin-layer dot ----
    // C layout: idx 0: (row g,   col 2*tig), 1: (row g, col 2*tig+1),
    //           idx 2: (row g+8, col 2*tig), 3: (row g+8, col 2*tig+1)
    float part0 = 0.f, part1 = 0.f;   // rows strip*16+g and +8
    #pragma unroll
    for (int p = 0; p < 8; p++) {
        #pragma unroll
        for (int idx = 0; idx < 4; idx++) {
            int j = (pb + p) * 8 + 2 * tig + (idx & 1);   // gate column 0..127
            float zin = Cz[p][idx] + s_bz[j];
            float hin = Ch[p][idx] + s_bh[j];
            float Z  = 1.f / (1.f + __expf(-zin));
            float Ht = tanhf(hin);
            float val = fmaxf((1.f - Z) * Ht, 0.f) * s_lw[j];
            if (idx & 2) part1 += val; else part0 += val;
        }
    }
    // reduce across the 4 threads of each group (same rows)
    part0 += __shfl_xor_sync(0xffffffffu, part0, 1);
    part0 += __shfl_xor_sync(0xffffffffu, part0, 2);
    part1 += __shfl_xor_sync(0xffffffffu, part1, 1);
    part1 += __shfl_xor_sync(0xffffffffu, part1, 2);
    if (tig == 0) {
        atomicAdd(&s_out[strip * 16 + g], part0);
        atomicAdd(&s_out[strip * 16 + g + 8], part1);
    }
    __syncthreads();
    if (tid < 128) {
        int node = node0 + tid;
        if (node < N_) out[node] = s_out[tid] + lb;
    }
}

// ---------------- verification: exact fp32 recompute of sampled outputs ----------------
// One block (128 threads) per sampled node (every 64th -> every GEMM CTA covered).
__global__ void __launch_bounds__(128) k_verify(
    const float* __restrict__ x,
    const float* __restrict__ Wxz, const float* __restrict__ Wxh,
    const float* __restrict__ bxz, const float* __restrict__ bhz,
    const float* __restrict__ bxh, const float* __restrict__ bhh,
    const float* __restrict__ linW, const float* __restrict__ linb,
    const float* __restrict__ out_tc)
{
    int node = blockIdx.x * 64;
    if (node >= N_) return;
    int j = threadIdx.x;

    __shared__ float sa[RDIM];
    __shared__ float red[128];
    for (int r = j; r < RDIM; r += 128) {
        int k = r >> 6, f = r & 63;
        const float* src = (k == 0) ? x : (k == 1) ? g_T1 : (k == 2) ? g_T2 : g_T3;
        sa[r] = src[(size_t)node * F_ + f];
    }
    __syncthreads();

    float z = 0.f, h = 0.f;
    for (int r = 0; r < RDIM; r++) {
        int k = r >> 6, f = r & 63;
        float a = sa[r];
        z += a * Wxz[(k * F_ + f) * H_ + j];
        h += a * Wxh[(k * F_ + f) * H_ + j];
    }
    z += bxz[j] + bhz[j];
    h += bxh[j] + bhh[j];
    float Z  = 1.f / (1.f + __expf(-z));
    float Ht = tanhf(h);
    red[j] = fmaxf((1.f - Z) * Ht, 0.f) * linW[j];
    __syncthreads();
    for (int s = 64; s > 0; s >>= 1) {
        if (j < s) red[j] += red[j + s];
        __syncthreads();
    }
    if (j == 0) {
        float ref = red[0] + linb[0];
        float got = out_tc[node];
        float tol = 1e-4f + 1e-3f * fabsf(ref);
        if (!(fabsf(got - ref) <= tol)) g_fail = 1;   // catches NaN too
    }
}

// ---------------- fallback: R1-proven FFMA f32x2 GEMM (runs only on mismatch) ----------------
__global__ void __launch_bounds__(128) k_gemm_fb(
    const float* __restrict__ x,
    const float* __restrict__ bxz, const float* __restrict__ bhz,
    const float* __restrict__ bxh, const float* __restrict__ bhh,
    const float* __restrict__ linW, const float* __restrict__ linb,
    float* __restrict__ out)
{
    if (g_fail == 0) return;   // mma result verified: nothing to do

    __shared__ __align__(16) float sA[32 * RDIM];
    const int node0 = blockIdx.x * 32;
    const int tid = threadIdx.x;

    for (int idx = tid; idx < 32 * RDIM; idx += 128) {
        int i = idx >> 8, r = idx & 255;
        int node = node0 + i;
        float v = 0.f;
        if (node < N_) {
            int k = r >> 6, f = r & 63;
            const float* src = (k == 0) ? x : (k == 1) ? g_T1 : (k == 2) ? g_T2 : g_T3;
            v = src[(size_t)node * F_ + f];
        }
        sA[idx] = v;
    }
    __syncthreads();

    unsigned long long az[32], ah[32];
    #pragma unroll
    for (int i = 0; i < 32; i++) { az[i] = 0ULL; ah[i] = 0ULL; }

    #pragma unroll 1
    for (int r = 0; r < RDIM; r += 4) {
        const int q = r >> 2;
        ulonglong2 w0 = *reinterpret_cast<const ulonglong2*>(&g_W4[q * 1024 + tid * 4]);
        ulonglong2 w1 = *reinterpret_cast<const ulonglong2*>(&g_W4[q * 1024 + (tid + 128) * 4]);
        #pragma unroll
        for (int i = 0; i < 32; i++) {
            ulonglong2 a2 = *reinterpret_cast<const ulonglong2*>(&sA[i * RDIM + r]);
            asm("fma.rn.f32x2 %0, %1, %2, %0;" : "+l"(az[i]) : "l"(a2.x), "l"(w0.x));
            asm("fma.rn.f32x2 %0, %1, %2, %0;" : "+l"(az[i]) : "l"(a2.y), "l"(w0.y));
            asm("fma.rn.f32x2 %0, %1, %2, %0;" : "+l"(ah[i]) : "l"(a2.x), "l"(w1.x));
            asm("fma.rn.f32x2 %0, %1, %2, %0;" : "+l"(ah[i]) : "l"(a2.y), "l"(w1.y));
        }
    }

    const float bz = bxz[tid] + bhz[tid];
    const float bh = bxh[tid] + bhh[tid];
    const float lw = linW[tid];
    __syncthreads();

    float* vals = sA;
    #pragma unroll
    for (int i = 0; i < 32; i++) {
        float zlo = __uint_as_float((unsigned)(az[i] & 0xffffffffULL));
        float zhi = __uint_as_float((unsigned)(az[i] >> 32));
        float hlo = __uint_as_float((unsigned)(ah[i] & 0xffffffffULL));
        float hhi = __uint_as_float((unsigned)(ah[i] >> 32));
        float zin = zlo + zhi + bz;
        float hin = hlo + hhi + bh;
        float Z  = 1.f / (1.f + __expf(-zin));
        float Ht = tanhf(hin);
        vals[i * 128 + tid] = fmaxf((1.f - Z) * Ht, 0.f) * lw;
    }
    __syncthreads();

    int i  = tid >> 2;
    int c4 = tid & 3;
    float s = 0.f;
    #pragma unroll
    for (int j = 0; j < 32; j++) {
        int jj = (j + tid) & 31;
        s += vals[i * 128 + c4 * 32 + jj];
    }
    s += __shfl_down_sync(0xffffffffu, s, 1);
    s += __shfl_down_sync(0xffffffffu, s, 2);
    if (c4 == 0) {
        int node = node0 + i;
        if (node < N_) out[node] = s + linb[0];
    }
}

// ---------------- launch ----------------
extern "C" void kernel_launch(void* const* d_in, const int* in_sizes, int n_in,
                              void* d_out, int out_size) {
    const float* x    = (const float*)d_in[0];
    const int*   ei   = (const int*)  d_in[1];
    const float* ew   = (const float*)d_in[2];
    const float* Wxz  = (const float*)d_in[3];
    const float* bxz  = (const float*)d_in[4];
    const float* bhz  = (const float*)d_in[6];   // Whz unused (h=0): bias only
    const float* Wxh  = (const float*)d_in[11];
    const float* bxh  = (const float*)d_in[12];
    const float* bhh  = (const float*)d_in[14];  // Whh unused (h=0): bias only
    const float* linW = (const float*)d_in[15];
    const float* linb = (const float*)d_in[16];
    float* out = (float*)d_out;

    cudaFuncSetAttribute(k_gemm_mma, cudaFuncAttributeMaxDynamicSharedMemorySize,
                         GEMM_DYN_BYTES);

    k_setup   <<<(CDIM * RDIM + 255) / 256, 256>>>(Wxz, Wxh);
    k_edge1   <<<(E_ + 255) / 256, 256>>>(ei, ew);
    k_disscan <<<50, 1024>>>();
    k_scatter <<<(E_ + 255) / 256, 256>>>(ei, ew);
    k_prop    <<<(N_ * 16 + 255) / 256, 256>>>(x, 0);
    k_prop    <<<(N_ * 16 + 255) / 256, 256>>>(x, 1);
    k_prop    <<<(N_ * 16 + 255) / 256, 256>>>(x, 2);
    k_gemm_mma<<<(N_ + 127) / 128, 512, GEMM_DYN_BYTES>>>(x, bxz, bhz, bxh, bhh,
                                                          linW, linb, out);
    k_verify  <<<(N_ + 63) / 64, 128>>>(x, Wxz, Wxh, bxz, bhz, bxh, bhh, linW, linb, out);
    k_gemm_fb <<<(N_ + 31) / 32, 128>>>(x, bxz, bhz, bxh, bhh, linW, linb, out);
}

// round 17
// speedup vs baseline: 1.0604x; 1.0604x over previous
#include <cuda_runtime.h>
#include <cstdint>

// Problem constants (fixed by the dataset)
#define N_  50000
#define E_  600000
#define F_  64
#define H_  128
#define RDIM 256     // GEMM K dim: 4 cheb orders * 64 feats
#define CDIM 256     // GEMM N dim: 128 (z) + 128 (h)
#define KC   32      // K chunk per SMEM stage
#define NCHUNK (RDIM / KC)   // 8

// ---------------- device scratch ----------------
__device__ float g_deg[N_];
__device__ int   g_cnt[N_];
__device__ int   g_cur[N_];
__device__ int   g_off[N_ + 1];
__device__ int   g_csrc[E_];
__device__ float g_cw[E_];
__device__ __align__(16) float g_T1[N_ * F_];
__device__ __align__(16) float g_T2[N_ * F_];
__device__ __align__(16) float g_T3[N_ * F_];
// B^T in tf32 bit patterns (hi and lo halves of the fp32 weights):
// g_Bt*[n*256 + kq], n = output col (0..255), kq = k*64+f  (= Wcat[kq][n])
__device__ __align__(16) uint32_t g_Bth[CDIM * RDIM];
__device__ __align__(16) uint32_t g_Btl[CDIM * RDIM];

// ---------------- helpers ----------------
__device__ __forceinline__ uint32_t f2tf32(float f) {
    uint32_t r; asm("cvt.rna.tf32.f32 %0, %1;" : "=r"(r) : "f"(f)); return r;
}

// Standard PTX (sm_80+) tensor-core MMA: D(16x8) += A(16x8,row) * B(8x8,col).
// tf32 inputs as .b32 bit patterns, fp32 accumulate.  (HW-verified R15.)
__device__ __forceinline__ void mma16n8k8(float* d, const uint32_t* a,
                                          uint32_t b0, uint32_t b1) {
    asm volatile(
        "mma.sync.aligned.m16n8k8.row.col.f32.tf32.tf32.f32 "
        "{%0,%1,%2,%3}, {%4,%5,%6,%7}, {%8,%9}, {%0,%1,%2,%3};"
        : "+f"(d[0]), "+f"(d[1]), "+f"(d[2]), "+f"(d[3])
        : "r"(a[0]), "r"(a[1]), "r"(a[2]), "r"(a[3]), "r"(b0), "r"(b1));
}

// ---------------- setup: zero arrays + build B^T hi/lo (tf32) ----------------
__global__ void k_setup(const float* __restrict__ Wxz, const float* __restrict__ Wxh) {
    int i = blockIdx.x * blockDim.x + threadIdx.x;
    if (i < N_) { g_deg[i] = 0.f; g_cnt[i] = 0; g_cur[i] = 0; }
    if (i < CDIM * RDIM) {
        int n = i >> 8, kq = i & 255;
        int k = kq >> 6, f = kq & 63;
        float v = (n < H_) ? Wxz[(k * F_ + f) * H_ + n]
                           : Wxh[(k * F_ + f) * H_ + (n - H_)];
        uint32_t hi = f2tf32(v);
        g_Bth[i] = hi;
        g_Btl[i] = f2tf32(v - __uint_as_float(hi));
    }
}

// deg (by src) + in-degree counts (by dst)
__global__ void k_edge1(const int* __restrict__ ei, const float* __restrict__ ew) {
    int e = blockIdx.x * blockDim.x + threadIdx.x;
    if (e >= E_) return;
    int s = ei[e], d = ei[E_ + e];
    float w = (s == d) ? 0.f : ew[e];
    if (w != 0.f) atomicAdd(&g_deg[s], w);
    atomicAdd(&g_cnt[d], 1);
}

// blocks 0..48: dis = rsqrt(deg); block 49: exclusive scan cnt -> off
__global__ void k_disscan() {
    if (blockIdx.x < 49) {
        int i = blockIdx.x * 1024 + threadIdx.x;
        if (i < N_) {
            float dg = g_deg[i];
            g_deg[i] = (dg > 0.f) ? rsqrtf(dg) : 0.f;
        }
        return;
    }
    const int TPB = 1024;
    __shared__ int ssum[TPB];
    int tid = threadIdx.x;
    const int chunk = (N_ + TPB - 1) / TPB;
    int beg = tid * chunk;
    int local = 0;
    for (int i = 0; i < chunk; i++) {
        int idx = beg + i;
        if (idx < N_) local += g_cnt[idx];
    }
    ssum[tid] = local;
    __syncthreads();
    for (int d = 1; d < TPB; d <<= 1) {
        int t = (tid >= d) ? ssum[tid - d] : 0;
        __syncthreads();
        if (tid >= d) ssum[tid] += t;
        __syncthreads();
    }
    int run = ssum[tid] - local;
    for (int i = 0; i < chunk; i++) {
        int idx = beg + i;
        if (idx < N_) { g_off[idx] = run; run += g_cnt[idx]; }
    }
    if (tid == TPB - 1) g_off[N_] = ssum[TPB - 1];
}

__global__ void k_scatter(const int* __restrict__ ei, const float* __restrict__ ew) {
    int e = blockIdx.x * blockDim.x + threadIdx.x;
    if (e >= E_) return;
    int s = ei[e], d = ei[E_ + e];
    float w = (s == d) ? 0.f : ew[e];
    float we = -g_deg[s] * w * g_deg[d];   // g_deg holds dis here
    int pos = atomicAdd(&g_cur[d], 1);
    int o = g_off[d] + pos;
    g_csrc[o] = s;
    g_cw[o]   = we;
}

// ---------------- Chebyshev propagation (gather, no float atomics) ----------------
__global__ void k_prop(const float* __restrict__ x, int step) {
    int t = blockIdx.x * blockDim.x + threadIdx.x;
    if (t >= N_ * 16) return;
    int node = t >> 4;
    int c    = (t & 15) << 2;

    const float* in;  const float* sub;  float* out;  float coef;
    if (step == 0)      { in = x;    sub = nullptr; out = g_T1; coef = 1.f; }
    else if (step == 1) { in = g_T1; sub = x;       out = g_T2; coef = 2.f; }
    else                { in = g_T2; sub = g_T1;    out = g_T3; coef = 2.f; }

    int beg = g_off[node], end = g_off[node + 1];
    float4 acc = make_float4(0.f, 0.f, 0.f, 0.f);
    for (int o = beg; o < end; o++) {
        int   s = g_csrc[o];
        float w = g_cw[o];
        float4 xv = *reinterpret_cast<const float4*>(in + (size_t)s * F_ + c);
        acc.x += w * xv.x; acc.y += w * xv.y;
        acc.z += w * xv.z; acc.w += w * xv.w;
    }
    float4 sv = make_float4(0.f, 0.f, 0.f, 0.f);
    if (sub) sv = *reinterpret_cast<const float4*>(sub + (size_t)node * F_ + c);
    float4 r;
    r.x = coef * acc.x - sv.x;  r.y = coef * acc.y - sv.y;
    r.z = coef * acc.z - sv.z;  r.w = coef * acc.w - sv.w;
    *reinterpret_cast<float4*>(out + (size_t)node * F_ + c) = r;
}

// ---------------- mma.sync tf32 GEMM + fused GRU epilogue (HW-verified R15) ----------------
// Per CTA (512 threads, 16 warps): M tile = 128 nodes, N = 256 (z||h), K = 256.
// 3-pass compensated tf32: D += Ahi*Bhi + Alo*Bhi + Ahi*Blo.
// Warp w: M-strip = (w&7)*16; tile pairs tp in [ (w>>3)*8, +8 ):
//   z-tile cols [tp*8, tp*8+8), h-tile cols [128+tp*8, ...). Pairing z/h in the
//   same thread lets the GRU epilogue combine them locally.
// SMEM (dynamic): A fp32 [128][33] | Bhi u32 [256][33] | Blo u32 [256][33]
#define A_PITCH 33
#define A_WORDS (128 * A_PITCH)          // 4224
#define B_WORDS (256 * A_PITCH)          // 8448
#define OFF_A   0
#define OFF_BH  (A_WORDS)
#define OFF_BL  (A_WORDS + B_WORDS)
#define GEMM_DYN_BYTES ((A_WORDS + 2 * B_WORDS) * 4)   // 84480

extern __shared__ __align__(16) uint32_t dynsm[];

__global__ void __launch_bounds__(512, 1) k_gemm_mma(
    const float* __restrict__ x,
    const float* __restrict__ bxz, const float* __restrict__ bhz,
    const float* __restrict__ bxh, const float* __restrict__ bhh,
    const float* __restrict__ linW, const float* __restrict__ linb,
    float* __restrict__ out)
{
    __shared__ float s_bz[H_], s_bh[H_], s_lw[H_], s_out[128];

    float* sA  = reinterpret_cast<float*>(dynsm + OFF_A);
    uint32_t* sBh = dynsm + OFF_BH;
    uint32_t* sBl = dynsm + OFF_BL;

    const int tid  = threadIdx.x;
    const int warp = tid >> 5;
    const int lane = tid & 31;
    const int g    = lane >> 2;       // group id (row within 8)
    const int tig  = lane & 3;        // thread in group (col within 4)
    const int strip = warp & 7;       // M strip: rows [strip*16, +16)
    const int pb    = (warp >> 3) * 8;  // first tile pair
    const int node0 = blockIdx.x * 128;

    if (tid < H_) {
        s_bz[tid] = bxz[tid] + bhz[tid];
        s_bh[tid] = bxh[tid] + bhh[tid];
        s_lw[tid] = linW[tid];
        s_out[tid] = 0.f;
    }
    const float lb = linb[0];

    float Cz[8][4], Ch[8][4];
    #pragma unroll
    for (int p = 0; p < 8; p++)
        #pragma unroll
        for (int i = 0; i < 4; i++) { Cz[p][i] = 0.f; Ch[p][i] = 0.f; }

    for (int c = 0; c < NCHUNK; c++) {
        const float* in = (c < 2) ? x : (c < 4) ? g_T1 : (c < 6) ? g_T2 : g_T3;
        int f0 = (c & 1) * KC;

        // stage A chunk: [128 rows][32 cols] fp32
        #pragma unroll
        for (int v = tid; v < 1024; v += 512) {
            int r = v >> 3, q = v & 7;
            int node = node0 + r;
            float4 a = make_float4(0.f, 0.f, 0.f, 0.f);
            if (node < N_)
                a = *reinterpret_cast<const float4*>(in + (size_t)node * F_ + f0 + q * 4);
            float* dst = sA + r * A_PITCH + q * 4;
            dst[0] = a.x; dst[1] = a.y; dst[2] = a.z; dst[3] = a.w;
        }
        // stage B chunk: [256 n][32 k] hi + lo
        #pragma unroll
        for (int u = tid; u < 2048; u += 512) {
            int n = u >> 3, q = u & 7;
            size_t gi = (size_t)n * RDIM + c * KC + q * 4;
            uint4 bh4 = *reinterpret_cast<const uint4*>(g_Bth + gi);
            uint4 bl4 = *reinterpret_cast<const uint4*>(g_Btl + gi);
            uint32_t* dh = sBh + n * A_PITCH + q * 4;
            uint32_t* dl = sBl + n * A_PITCH + q * 4;
            dh[0] = bh4.x; dh[1] = bh4.y; dh[2] = bh4.z; dh[3] = bh4.w;
            dl[0] = bl4.x; dl[1] = bl4.y; dl[2] = bl4.z; dl[3] = bl4.w;
        }
        __syncthreads();

        // A fragments for the 4 k-steps (hi/lo tf32)
        uint32_t ahi[4][4], alo[4][4];
        #pragma unroll
        for (int kk = 0; kk < 4; kk++) {
            int base = (strip * 16 + g) * A_PITCH + kk * 8 + tig;
            float a0 = sA[base];                  // row g,   col tig
            float a1 = sA[base + 8 * A_PITCH];    // row g+8, col tig
            float a2 = sA[base + 4];              // row g,   col tig+4
            float a3 = sA[base + 8 * A_PITCH + 4];
            ahi[kk][0] = f2tf32(a0); alo[kk][0] = f2tf32(a0 - __uint_as_float(ahi[kk][0]));
            ahi[kk][1] = f2tf32(a1); alo[kk][1] = f2tf32(a1 - __uint_as_float(ahi[kk][1]));
            ahi[kk][2] = f2tf32(a2); alo[kk][2] = f2tf32(a2 - __uint_as_float(ahi[kk][2]));
            ahi[kk][3] = f2tf32(a3); alo[kk][3] = f2tf32(a3 - __uint_as_float(ahi[kk][3]));
        }

        #pragma unroll
        for (int p = 0; p < 8; p++) {
            int nz = (pb + p) * 8;        // z-tile col base
            int nh = 128 + (pb + p) * 8;  // h-tile col base
            #pragma unroll
            for (int kk = 0; kk < 4; kk++) {
                int bo = kk * 8 + tig;
                // z tile
                {
                    int bi = (nz + g) * A_PITCH + bo;
                    uint32_t bh0 = sBh[bi], bh1 = sBh[bi + 4];
                    mma16n8k8(Cz[p], ahi[kk], bh0, bh1);
                    mma16n8k8(Cz[p], alo[kk], bh0, bh1);
                    uint32_t bl0 = sBl[bi], bl1 = sBl[bi + 4];
                    mma16n8k8(Cz[p], ahi[kk], bl0, bl1);
                }
                // h tile
                {
                    int bi = (nh + g) * A_PITCH + bo;
                    uint32_t bh0 = sBh[bi], bh1 = sBh[bi + 4];
                    mma16n8k8(Ch[p], ahi[kk], bh0, bh1);
                    mma16n8k8(Ch[p], alo[kk], bh0, bh1);
                    uint32_t bl0 = sBl[bi], bl1 = sBl[bi + 4];
                    mma16n8k8(Ch[p], ahi[kk], bl0, bl1);
                }
            }
        }
        __syncthreads();
    }

    // ---- fused GRU epilogue + lin-layer dot ----
    // C layout: idx 0: (row g,   col 2*tig), 1: (row g, col 2*tig+1),
    //           idx 2: (row g+8, col 2*tig), 3: (row g+8, col 2*tig+1)
    float part0 = 0.f, part1 = 0.f;   // rows strip*16+g and +8
    #pragma unroll
    for (int p = 0; p < 8; p++) {
        #pragma unroll
        for (int idx = 0; idx < 4; idx++) {
            int j = (pb + p) * 8 + 2 * tig + (idx & 1);   // gate column 0..127
            float zin = Cz[p][idx] + s_bz[j];
            float hin = Ch[p][idx] + s_bh[j];
            float Z  = 1.f / (1.f + __expf(-zin));
            float Ht = tanhf(hin);
            float val = fmaxf((1.f - Z) * Ht, 0.f) * s_lw[j];
            if (idx & 2) part1 += val; else part0 += val;
        }
    }
    // reduce across the 4 threads of each group (same rows)
    part0 += __shfl_xor_sync(0xffffffffu, part0, 1);
    part0 += __shfl_xor_sync(0xffffffffu, part0, 2);
    part1 += __shfl_xor_sync(0xffffffffu, part1, 1);
    part1 += __shfl_xor_sync(0xffffffffu, part1, 2);
    if (tig == 0) {
        atomicAdd(&s_out[strip * 16 + g], part0);
        atomicAdd(&s_out[strip * 16 + g + 8], part1);
    }
    __syncthreads();
    if (tid < 128) {
        int node = node0 + tid;
        if (node < N_) out[node] = s_out[tid] + lb;
    }
}

// ---------------- launch ----------------
extern "C" void kernel_launch(void* const* d_in, const int* in_sizes, int n_in,
                              void* d_out, int out_size) {
    const float* x    = (const float*)d_in[0];
    const int*   ei   = (const int*)  d_in[1];
    const float* ew   = (const float*)d_in[2];
    const float* Wxz  = (const float*)d_in[3];
    const float* bxz  = (const float*)d_in[4];
    const float* bhz  = (const float*)d_in[6];   // Whz unused (h=0): bias only
    const float* Wxh  = (const float*)d_in[11];
    const float* bxh  = (const float*)d_in[12];
    const float* bhh  = (const float*)d_in[14];  // Whh unused (h=0): bias only
    const float* linW = (const float*)d_in[15];
    const float* linb = (const float*)d_in[16];
    float* out = (float*)d_out;

    cudaFuncSetAttribute(k_gemm_mma, cudaFuncAttributeMaxDynamicSharedMemorySize,
                         GEMM_DYN_BYTES);

    k_setup   <<<(CDIM * RDIM + 255) / 256, 256>>>(Wxz, Wxh);
    k_edge1   <<<(E_ + 255) / 256, 256>>>(ei, ew);
    k_disscan <<<50, 1024>>>();
    k_scatter <<<(E_ + 255) / 256, 256>>>(ei, ew);
    k_prop    <<<(N_ * 16 + 255) / 256, 256>>>(x, 0);
    k_prop    <<<(N_ * 16 + 255) / 256, 256>>>(x, 1);
    k_prop    <<<(N_ * 16 + 255) / 256, 256>>>(x, 2);
    k_gemm_mma<<<(N_ + 127) / 128, 512, GEMM_DYN_BYTES>>>(x, bxz, bhz, bxh, bhh,
                                                          linW, linb, out);
}